// round 1
// baseline (speedup 1.0000x reference)
#include <cuda_runtime.h>

#define BB    256
#define IN_F  1024
#define OUT_F 128
#define KD    16
#define NCOL  (OUT_F * KD)          // 2048
#define OUTW  (IN_F + OUT_F)        // 1152

// scratch: m = x @ t, [256][128][16] fp32 = 2 MB
__device__ float d_m[BB * NCOL];

// ---------------------------------------------------------------------------
// GEMM: C[256x2048] = A[256x1024] * B[1024x2048], fp32
// 64x64 tile, BK=16, 4x4 per thread, 256 threads/block
// ---------------------------------------------------------------------------
__global__ __launch_bounds__(256) void gemm_kernel(
    const float* __restrict__ A,   // x  [256][1024]
    const float* __restrict__ Bm,  // t  [1024][2048]
    float* __restrict__ C)         // m  [256][2048]
{
    const int BM = 64, BN = 64, BK = 16;
    __shared__ float As[BK][72];   // [k][row], padded: 72*4B=288B, 16B-aligned rows
    __shared__ float Bs[BK][BN];   // [k][col]

    int tid = threadIdx.x;
    int tx = tid & 15;             // 0..15 (col group)
    int ty = tid >> 4;             // 0..15 (row group)
    int rm0 = blockIdx.y * BM;
    int cn0 = blockIdx.x * BN;

    // load mapping
    int a_row = tid >> 2;          // 0..63
    int a_col = (tid & 3) << 2;    // 0,4,8,12
    int b_row = tid >> 4;          // 0..15
    int b_col = (tid & 15) << 2;   // 0..60

    float acc[4][4];
#pragma unroll
    for (int i = 0; i < 4; i++)
#pragma unroll
        for (int j = 0; j < 4; j++) acc[i][j] = 0.0f;

    for (int k0 = 0; k0 < IN_F; k0 += BK) {
        float4 av = *(const float4*)&A[(rm0 + a_row) * IN_F + k0 + a_col];
        As[a_col + 0][a_row] = av.x;
        As[a_col + 1][a_row] = av.y;
        As[a_col + 2][a_row] = av.z;
        As[a_col + 3][a_row] = av.w;
        float4 bv = *(const float4*)&Bm[(k0 + b_row) * NCOL + cn0 + b_col];
        *(float4*)&Bs[b_row][b_col] = bv;
        __syncthreads();

#pragma unroll
        for (int kk = 0; kk < BK; kk++) {
            float4 a = *(const float4*)&As[kk][ty << 2];
            float4 b = *(const float4*)&Bs[kk][tx << 2];
            acc[0][0] += a.x * b.x; acc[0][1] += a.x * b.y; acc[0][2] += a.x * b.z; acc[0][3] += a.x * b.w;
            acc[1][0] += a.y * b.x; acc[1][1] += a.y * b.y; acc[1][2] += a.y * b.z; acc[1][3] += a.y * b.w;
            acc[2][0] += a.z * b.x; acc[2][1] += a.z * b.y; acc[2][2] += a.z * b.z; acc[2][3] += a.z * b.w;
            acc[3][0] += a.w * b.x; acc[3][1] += a.w * b.y; acc[3][2] += a.w * b.z; acc[3][3] += a.w * b.w;
        }
        __syncthreads();
    }

#pragma unroll
    for (int i = 0; i < 4; i++) {
        float4 v = make_float4(acc[i][0], acc[i][1], acc[i][2], acc[i][3]);
        *(float4*)&C[(rm0 + (ty << 2) + i) * NCOL + cn0 + (tx << 2)] = v;
    }
}

// ---------------------------------------------------------------------------
// Pairwise: for each o (block), each thread owns b1; loop b2 over 256 rows in
// shared (broadcast reads), accumulate exp(-L1), subtract self term.
// smem row padded to 20 floats -> conflict-free 16B-stride LDS/STS
// ---------------------------------------------------------------------------
__global__ __launch_bounds__(256) void pair_kernel(float* __restrict__ out)
{
    __shared__ float4 sm[BB][5];   // 20 floats per row (16 used)

    int o  = blockIdx.x;           // 0..127
    int b1 = threadIdx.x;          // 0..255

    const float4* mp = (const float4*)(d_m + b1 * NCOL + o * KD);
    float4 a0 = mp[0], a1 = mp[1], a2 = mp[2], a3 = mp[3];
    sm[b1][0] = a0; sm[b1][1] = a1; sm[b1][2] = a2; sm[b1][3] = a3;
    __syncthreads();

    float acc = 0.0f;
#pragma unroll 4
    for (int b2 = 0; b2 < BB; b2++) {
        float4 c0 = sm[b2][0], c1 = sm[b2][1], c2 = sm[b2][2], c3 = sm[b2][3];
        float s;
        s  = fabsf(a0.x - c0.x); s += fabsf(a0.y - c0.y);
        s += fabsf(a0.z - c0.z); s += fabsf(a0.w - c0.w);
        s += fabsf(a1.x - c1.x); s += fabsf(a1.y - c1.y);
        s += fabsf(a1.z - c1.z); s += fabsf(a1.w - c1.w);
        s += fabsf(a2.x - c2.x); s += fabsf(a2.y - c2.y);
        s += fabsf(a2.z - c2.z); s += fabsf(a2.w - c2.w);
        s += fabsf(a3.x - c3.x); s += fabsf(a3.y - c3.y);
        s += fabsf(a3.z - c3.z); s += fabsf(a3.w - c3.w);
        acc += __expf(-s);
    }

    // self pair contributes exp(0) = 1
    out[b1 * OUTW + IN_F + o] = acc - 1.0f;
}

// ---------------------------------------------------------------------------
// x passthrough: out[b][0:1024] = x[b][:]
// ---------------------------------------------------------------------------
__global__ __launch_bounds__(256) void copy_x_kernel(
    const float* __restrict__ x, float* __restrict__ out)
{
    int b = blockIdx.x;
    int j = threadIdx.x;          // 0..255, 4 floats each
    const float4* src = (const float4*)(x + b * IN_F);
    float4*       dst = (float4*)(out + b * OUTW);
    dst[j] = src[j];
}

extern "C" void kernel_launch(void* const* d_in, const int* in_sizes, int n_in,
                              void* d_out, int out_size)
{
    const float* x = (const float*)d_in[0];     // [256][1024]
    const float* t = (const float*)d_in[1];     // [1024][128][16] = [1024][2048]
    float* out = (float*)d_out;                 // [256][1152]

    float* m;
    cudaGetSymbolAddress((void**)&m, d_m);

    dim3 ggrid(NCOL / 64, BB / 64);             // (32, 4)
    gemm_kernel<<<ggrid, 256>>>(x, t, m);
    copy_x_kernel<<<BB, 256>>>(x, out);
    pair_kernel<<<OUT_F, 256>>>(out);
}

// round 2
// speedup vs baseline: 1.5118x; 1.5118x over previous
#include <cuda_runtime.h>
#include <cstdint>

#define BB    256
#define IN_F  1024
#define OUT_F 128
#define KD    16
#define NCOL  (OUT_F * KD)          // 2048
#define OUTW  (IN_F + OUT_F)        // 1152

#define BM    64
#define BN    64
#define BKK   32
#define NKT   (IN_F / BKK)          // 32

// scratch: m = x @ t, [256][2048] fp32 = 2 MB
__device__ float d_m[BB * NCOL];

__device__ __forceinline__ unsigned long long addx2(unsigned long long a,
                                                    unsigned long long b) {
    unsigned long long r;
    asm("add.rn.f32x2 %0, %1, %2;" : "=l"(r) : "l"(a), "l"(b));
    return r;
}

// ---------------------------------------------------------------------------
// GEMM via mma.sync m16n8k8 tf32: C[256x2048] = A[256x1024] * B[1024x2048]
// Block 64x64, BK=32, 128 threads (4 warps, 2x2), warp tile 32x32.
// Double-buffered smem, padded strides (A:36, B:72) for conflict-free LDS.
// ---------------------------------------------------------------------------
__global__ __launch_bounds__(128) void gemm_tf32_kernel(
    const float* __restrict__ A,   // x  [256][1024]
    const float* __restrict__ B,   // t  [1024][2048]
    float* __restrict__ C)         // m  [256][2048]
{
    __shared__ float As[2][BM * 36];   // [m][k], stride 36
    __shared__ float Bs[2][BKK * 72];  // [k][n], stride 72

    const int tid  = threadIdx.x;
    const int lane = tid & 31;
    const int wid  = tid >> 5;
    const int g    = lane >> 2;        // groupID 0..7
    const int t    = lane & 3;         // threadID-in-group 0..3
    const int wm   = (wid >> 1) * 32;  // warp m offset
    const int wn   = (wid & 1) * 32;   // warp n offset
    const int bm0  = blockIdx.y * BM;
    const int bn0  = blockIdx.x * BN;

    // global->reg staging mapping
    const int arow = tid >> 3;         // 0..15 (+i*16)
    const int acol = (tid & 7) * 4;    // 0..28
    const int brow = tid >> 4;         // 0..7  (+i*8)
    const int bcol = (tid & 15) * 4;   // 0..60

    float acc[2][4][4];
#pragma unroll
    for (int mf = 0; mf < 2; mf++)
#pragma unroll
        for (int nf = 0; nf < 4; nf++)
#pragma unroll
            for (int i = 0; i < 4; i++) acc[mf][nf][i] = 0.0f;

    float4 aR[4], bR[4];

    auto fetch = [&](int k0) {
#pragma unroll
        for (int i = 0; i < 4; i++)
            aR[i] = *(const float4*)&A[(bm0 + arow + i * 16) * IN_F + k0 + acol];
#pragma unroll
        for (int i = 0; i < 4; i++)
            bR[i] = *(const float4*)&B[(k0 + brow + i * 8) * NCOL + bn0 + bcol];
    };
    auto store = [&](int buf) {
#pragma unroll
        for (int i = 0; i < 4; i++)
            *(float4*)&As[buf][(arow + i * 16) * 36 + acol] = aR[i];
#pragma unroll
        for (int i = 0; i < 4; i++)
            *(float4*)&Bs[buf][(brow + i * 8) * 72 + bcol] = bR[i];
    };

    fetch(0);
    store(0);
    __syncthreads();

#pragma unroll 1
    for (int kt = 0; kt < NKT; kt++) {
        const int cur = kt & 1;
        if (kt + 1 < NKT) fetch((kt + 1) * BKK);

#pragma unroll
        for (int ks = 0; ks < 4; ks++) {
            const int k = ks * 8;
            uint32_t ua[2][4], ub[4][2];
#pragma unroll
            for (int mf = 0; mf < 2; mf++) {
                const float* ap = &As[cur][(wm + mf * 16) * 36 + k];
                ua[mf][0] = __float_as_uint(ap[g * 36 + t]);
                ua[mf][1] = __float_as_uint(ap[(g + 8) * 36 + t]);
                ua[mf][2] = __float_as_uint(ap[g * 36 + t + 4]);
                ua[mf][3] = __float_as_uint(ap[(g + 8) * 36 + t + 4]);
            }
#pragma unroll
            for (int nf = 0; nf < 4; nf++) {
                const float* bp = &Bs[cur][k * 72 + wn + nf * 8 + g];
                ub[nf][0] = __float_as_uint(bp[t * 72]);
                ub[nf][1] = __float_as_uint(bp[(t + 4) * 72]);
            }
#pragma unroll
            for (int mf = 0; mf < 2; mf++)
#pragma unroll
                for (int nf = 0; nf < 4; nf++) {
                    asm volatile(
                        "mma.sync.aligned.m16n8k8.row.col.f32.tf32.tf32.f32 "
                        "{%0,%1,%2,%3}, {%4,%5,%6,%7}, {%8,%9}, {%0,%1,%2,%3};\n"
                        : "+f"(acc[mf][nf][0]), "+f"(acc[mf][nf][1]),
                          "+f"(acc[mf][nf][2]), "+f"(acc[mf][nf][3])
                        : "r"(ua[mf][0]), "r"(ua[mf][1]),
                          "r"(ua[mf][2]), "r"(ua[mf][3]),
                          "r"(ub[nf][0]), "r"(ub[nf][1]));
                }
        }

        if (kt + 1 < NKT) store(cur ^ 1);
        __syncthreads();
    }

#pragma unroll
    for (int mf = 0; mf < 2; mf++)
#pragma unroll
        for (int nf = 0; nf < 4; nf++) {
            const int r0 = bm0 + wm + mf * 16 + g;
            const int c0 = bn0 + wn + nf * 8 + t * 2;
            *(float2*)&C[r0 * NCOL + c0] =
                make_float2(acc[mf][nf][0], acc[mf][nf][1]);
            *(float2*)&C[(r0 + 8) * NCOL + c0] =
                make_float2(acc[mf][nf][2], acc[mf][nf][3]);
        }
}

// ---------------------------------------------------------------------------
// Pairwise exp(-L1): packed f32x2 math. smem holds NEGATED rows so
// diff = a + (-c) is one packed add; abs via 64-bit AND (alu pipe).
// One block per o, thread = b1, loop b2 over smem broadcast reads.
// ---------------------------------------------------------------------------
__global__ __launch_bounds__(256) void pair_kernel(
    const float* __restrict__ m, float* __restrict__ out)
{
    __shared__ ulonglong2 sm[BB][4];   // negated rows, 32B each

    const int o  = blockIdx.x;
    const int b1 = threadIdx.x;

    const ulonglong2* mp = (const ulonglong2*)(m + b1 * NCOL + o * KD);
    unsigned long long a[8];
#pragma unroll
    for (int i = 0; i < 4; i++) {
        ulonglong2 q = mp[i];
        a[2 * i]     = q.x;
        a[2 * i + 1] = q.y;
    }
    const unsigned long long SGN = 0x8000000080000000ULL;
#pragma unroll
    for (int i = 0; i < 4; i++)
        sm[b1][i] = make_ulonglong2(a[2 * i] ^ SGN, a[2 * i + 1] ^ SGN);
    __syncthreads();

    const unsigned long long MSK = 0x7FFFFFFF7FFFFFFFULL;
    float tot = 0.0f;
#pragma unroll 2
    for (int b2 = 0; b2 < BB; b2++) {
        unsigned long long d[8];
#pragma unroll
        for (int j = 0; j < 4; j++) {
            ulonglong2 c = sm[b2][j];
            d[2 * j]     = addx2(a[2 * j],     c.x) & MSK;
            d[2 * j + 1] = addx2(a[2 * j + 1], c.y) & MSK;
        }
        unsigned long long e0 = addx2(d[0], d[1]);
        unsigned long long e1 = addx2(d[2], d[3]);
        unsigned long long e2 = addx2(d[4], d[5]);
        unsigned long long e3 = addx2(d[6], d[7]);
        unsigned long long f0 = addx2(e0, e1);
        unsigned long long f1 = addx2(e2, e3);
        unsigned long long gs = addx2(f0, f1);
        uint32_t glo, ghi;
        asm("mov.b64 {%0,%1}, %2;" : "=r"(glo), "=r"(ghi) : "l"(gs));
        float s = __uint_as_float(glo) + __uint_as_float(ghi);
        tot += __expf(-s);
    }

    out[b1 * OUTW + IN_F + o] = tot - 1.0f;   // remove self pair (exp(0)=1)
}

// ---------------------------------------------------------------------------
// x passthrough
// ---------------------------------------------------------------------------
__global__ __launch_bounds__(256) void copy_x_kernel(
    const float* __restrict__ x, float* __restrict__ out)
{
    int b = blockIdx.x;
    int j = threadIdx.x;
    const float4* src = (const float4*)(x + b * IN_F);
    float4*       dst = (float4*)(out + b * OUTW);
    dst[j] = src[j];
}

extern "C" void kernel_launch(void* const* d_in, const int* in_sizes, int n_in,
                              void* d_out, int out_size)
{
    const float* x = (const float*)d_in[0];     // [256][1024]
    const float* t = (const float*)d_in[1];     // [1024][2048]
    float* out = (float*)d_out;                 // [256][1152]

    float* m;
    cudaGetSymbolAddress((void**)&m, d_m);

    dim3 ggrid(NCOL / BN, BB / BM);             // (32, 4) = 128 blocks
    gemm_tf32_kernel<<<ggrid, 128>>>(x, t, m);
    copy_x_kernel<<<BB, 256>>>(x, out);
    pair_kernel<<<OUT_F, 256>>>(m, out);
}

// round 3
// speedup vs baseline: 1.9263x; 1.2742x over previous
#include <cuda_runtime.h>
#include <cstdint>

#define BB     256
#define IN_F   1024
#define OUT_F  128
#define KD     16
#define NCOL   (OUT_F * KD)        // 2048
#define OUTW   (IN_F + OUT_F)      // 1152

#define SPLITS 4
#define KSPLIT (IN_F / SPLITS)     // 256
#define BM     64
#define BN     64
#define BKK    32
#define NKT    (KSPLIT / BKK)      // 8

// GEMM partials: [SPLITS][256][2048] fp32 = 8 MB
__device__ float d_part[SPLITS * BB * NCOL];

__device__ __forceinline__ unsigned long long addx2(unsigned long long a,
                                                    unsigned long long b) {
    unsigned long long r;
    asm("add.rn.f32x2 %0, %1, %2;" : "=l"(r) : "l"(a), "l"(b));
    return r;
}

__device__ __forceinline__ void cp16(uint32_t smem, const void* gmem) {
    asm volatile("cp.async.cg.shared.global [%0], [%1], 16;"
                 :: "r"(smem), "l"(gmem));
}

// ---------------------------------------------------------------------------
// GEMM via mma.sync m16n8k8 tf32, split-K x4.
// grid (32, 4, 5): z<4 = compute (64x64 tile, K slice of 256, 128 thr),
//                  z==4 = x-passthrough copy + "-1" init of o_b region.
// cp.async double-buffered smem, padded strides (A:36, B:72).
// ---------------------------------------------------------------------------
__global__ __launch_bounds__(128) void gemm_tf32_kernel(
    const float* __restrict__ A,   // x  [256][1024]
    const float* __restrict__ B,   // t  [1024][2048]
    float* __restrict__ C,         // d_part
    float* __restrict__ out)       // [256][1152]
{
    const int tid = threadIdx.x;

    if (blockIdx.z == SPLITS) {
        // ---- copy/init blocks: 128 blocks, 2 rows each ----
        const int id = blockIdx.y * gridDim.x + blockIdx.x;  // 0..127
#pragma unroll
        for (int rr = 0; rr < 2; rr++) {
            const int r = id * 2 + rr;
            const float4* src = (const float4*)(A + r * IN_F);
            float4*       dst = (float4*)(out + r * OUTW);
            dst[tid]       = src[tid];
            dst[tid + 128] = src[tid + 128];
            if (tid < 32)   // self-pair correction: o_b starts at -1
                ((float4*)(out + r * OUTW + IN_F))[tid] =
                    make_float4(-1.f, -1.f, -1.f, -1.f);
        }
        return;
    }

    __shared__ float As[2][BM * 36];
    __shared__ float Bs[2][BKK * 72];

    const int lane = tid & 31;
    const int wid  = tid >> 5;
    const int g    = lane >> 2;
    const int t    = lane & 3;
    const int wm   = (wid >> 1) * 32;
    const int wn   = (wid & 1) * 32;
    const int bm0  = blockIdx.y * BM;
    const int bn0  = blockIdx.x * BN;
    const int koff = blockIdx.z * KSPLIT;

    const int arow = tid >> 3;         // 0..15 (+16i)
    const int acol = (tid & 7) * 4;
    const int brow = tid >> 4;         // 0..7  (+8i)
    const int bcol = (tid & 15) * 4;

    uint32_t as_b[2], bs_b[2];
#pragma unroll
    for (int b = 0; b < 2; b++) {
        as_b[b] = (uint32_t)__cvta_generic_to_shared(&As[b][0]);
        bs_b[b] = (uint32_t)__cvta_generic_to_shared(&Bs[b][0]);
    }

    auto fetch = [&](int buf, int k0) {
#pragma unroll
        for (int i = 0; i < 4; i++)
            cp16(as_b[buf] + (((arow + i * 16) * 36 + acol) << 2),
                 &A[(bm0 + arow + i * 16) * IN_F + k0 + acol]);
#pragma unroll
        for (int i = 0; i < 4; i++)
            cp16(bs_b[buf] + (((brow + i * 8) * 72 + bcol) << 2),
                 &B[(k0 + brow + i * 8) * NCOL + bn0 + bcol]);
        asm volatile("cp.async.commit_group;");
    };

    float acc[2][4][4];
#pragma unroll
    for (int mf = 0; mf < 2; mf++)
#pragma unroll
        for (int nf = 0; nf < 4; nf++)
#pragma unroll
            for (int i = 0; i < 4; i++) acc[mf][nf][i] = 0.0f;

    fetch(0, koff);

#pragma unroll 1
    for (int kt = 0; kt < NKT; kt++) {
        if (kt + 1 < NKT) {
            fetch((kt + 1) & 1, koff + (kt + 1) * BKK);
            asm volatile("cp.async.wait_group 1;");
        } else {
            asm volatile("cp.async.wait_group 0;");
        }
        __syncthreads();
        const int cur = kt & 1;

#pragma unroll
        for (int ks = 0; ks < 4; ks++) {
            const int k = ks * 8;
            uint32_t ua[2][4], ub[4][2];
#pragma unroll
            for (int mf = 0; mf < 2; mf++) {
                const float* ap = &As[cur][(wm + mf * 16) * 36 + k];
                ua[mf][0] = __float_as_uint(ap[g * 36 + t]);
                ua[mf][1] = __float_as_uint(ap[(g + 8) * 36 + t]);
                ua[mf][2] = __float_as_uint(ap[g * 36 + t + 4]);
                ua[mf][3] = __float_as_uint(ap[(g + 8) * 36 + t + 4]);
            }
#pragma unroll
            for (int nf = 0; nf < 4; nf++) {
                const float* bp = &Bs[cur][k * 72 + wn + nf * 8 + g];
                ub[nf][0] = __float_as_uint(bp[t * 72]);
                ub[nf][1] = __float_as_uint(bp[(t + 4) * 72]);
            }
#pragma unroll
            for (int mf = 0; mf < 2; mf++)
#pragma unroll
                for (int nf = 0; nf < 4; nf++) {
                    asm volatile(
                        "mma.sync.aligned.m16n8k8.row.col.f32.tf32.tf32.f32 "
                        "{%0,%1,%2,%3}, {%4,%5,%6,%7}, {%8,%9}, {%0,%1,%2,%3};\n"
                        : "+f"(acc[mf][nf][0]), "+f"(acc[mf][nf][1]),
                          "+f"(acc[mf][nf][2]), "+f"(acc[mf][nf][3])
                        : "r"(ua[mf][0]), "r"(ua[mf][1]),
                          "r"(ua[mf][2]), "r"(ua[mf][3]),
                          "r"(ub[nf][0]), "r"(ub[nf][1]));
                }
        }
        __syncthreads();
    }

    float* Cz = C + blockIdx.z * BB * NCOL;
#pragma unroll
    for (int mf = 0; mf < 2; mf++)
#pragma unroll
        for (int nf = 0; nf < 4; nf++) {
            const int r0 = bm0 + wm + mf * 16 + g;
            const int c0 = bn0 + wn + nf * 8 + t * 2;
            *(float2*)&Cz[r0 * NCOL + c0] =
                make_float2(acc[mf][nf][0], acc[mf][nf][1]);
            *(float2*)&Cz[(r0 + 8) * NCOL + c0] =
                make_float2(acc[mf][nf][2], acc[mf][nf][3]);
        }
}

// ---------------------------------------------------------------------------
// Pairwise exp(-L1), packed f32x2. grid (128 o, 2 b2-halves), 256 threads.
// Each thread owns b1: sums the 4 GEMM partials for its row, stages negated
// rows of its b2-half in smem, loops 128 b2, atomicAdds onto out (init -1).
// ---------------------------------------------------------------------------
__global__ __launch_bounds__(256) void pair_kernel(
    const float* __restrict__ part, float* __restrict__ out)
{
    __shared__ ulonglong2 sm[128][4];

    const int o  = blockIdx.x;
    const int s  = blockIdx.y;
    const int b1 = threadIdx.x;

    const ulonglong2* p0 = (const ulonglong2*)(part + b1 * NCOL + o * KD);
    ulonglong2 q[4];
#pragma unroll
    for (int i = 0; i < 4; i++) q[i] = p0[i];
#pragma unroll
    for (int sp = 1; sp < SPLITS; sp++) {
        const ulonglong2* ps =
            (const ulonglong2*)(part + sp * BB * NCOL + b1 * NCOL + o * KD);
#pragma unroll
        for (int i = 0; i < 4; i++) {
            ulonglong2 v = ps[i];
            q[i].x = addx2(q[i].x, v.x);
            q[i].y = addx2(q[i].y, v.y);
        }
    }

    unsigned long long a[8];
#pragma unroll
    for (int i = 0; i < 4; i++) { a[2 * i] = q[i].x; a[2 * i + 1] = q[i].y; }

    const unsigned long long SGN = 0x8000000080000000ULL;
    const int lb = b1 - s * 128;
    if ((unsigned)lb < 128u) {
#pragma unroll
        for (int i = 0; i < 4; i++)
            sm[lb][i] = make_ulonglong2(a[2 * i] ^ SGN, a[2 * i + 1] ^ SGN);
    }
    __syncthreads();

    const unsigned long long MSK = 0x7FFFFFFF7FFFFFFFULL;
    float tot = 0.0f;
#pragma unroll 2
    for (int b2 = 0; b2 < 128; b2++) {
        unsigned long long d[8];
#pragma unroll
        for (int j = 0; j < 4; j++) {
            ulonglong2 c = sm[b2][j];
            d[2 * j]     = addx2(a[2 * j],     c.x) & MSK;
            d[2 * j + 1] = addx2(a[2 * j + 1], c.y) & MSK;
        }
        unsigned long long e0 = addx2(d[0], d[1]);
        unsigned long long e1 = addx2(d[2], d[3]);
        unsigned long long e2 = addx2(d[4], d[5]);
        unsigned long long e3 = addx2(d[6], d[7]);
        unsigned long long f0 = addx2(e0, e1);
        unsigned long long f1 = addx2(e2, e3);
        unsigned long long gs = addx2(f0, f1);
        uint32_t glo, ghi;
        asm("mov.b64 {%0,%1}, %2;" : "=r"(glo), "=r"(ghi) : "l"(gs));
        float sum = __uint_as_float(glo) + __uint_as_float(ghi);
        tot += __expf(-sum);
    }

    atomicAdd(&out[b1 * OUTW + IN_F + o], tot);
}

extern "C" void kernel_launch(void* const* d_in, const int* in_sizes, int n_in,
                              void* d_out, int out_size)
{
    const float* x = (const float*)d_in[0];     // [256][1024]
    const float* t = (const float*)d_in[1];     // [1024][2048]
    float* out = (float*)d_out;                 // [256][1152]

    float* part;
    cudaGetSymbolAddress((void**)&part, d_part);

    dim3 ggrid(NCOL / BN, BB / BM, SPLITS + 1);  // (32, 4, 5) = 640 blocks
    gemm_tf32_kernel<<<ggrid, 128>>>(x, t, part, out);
    pair_kernel<<<dim3(OUT_F, 2), 256>>>(part, out);
}